// round 3
// baseline (speedup 1.0000x reference)
#include <cuda_runtime.h>
#include <math.h>

// LSEP loss: out = log1p( sum_rows (sum_{t==0} e^x) * (sum_{t>0} e^{-x}) )
// input: [32768, 1000] fp32, target: [32768, 1000] int32, out: [1] fp32.
//
// HBM-bound: 262 MB read -> ~33us floor at 8 TB/s.
// Warp-per-row, float4/int4 loads, one __expf per element, branchless
// select accumulation, warp shuffle reduction, one double atomicAdd per
// block (4096 total). g_total is zeroed at the END of each launch (in
// finalize): 0 -> sum -> 0 per launch, deterministic and graph-replay-safe.

#define ROWS 32768
#define COLS 1000
#define VEC4_PER_ROW (COLS / 4)   // 250
#define WARPS_PER_BLOCK 8
#define THREADS (WARPS_PER_BLOCK * 32)

__device__ double g_total;   // static-initialized to 0; finalize resets it to 0

__global__ __launch_bounds__(THREADS) void lsep_main_kernel(
    const float* __restrict__ input,
    const int* __restrict__ target)
{
    const int warp = threadIdx.x >> 5;
    const int lane = threadIdx.x & 31;
    const int row  = blockIdx.x * WARPS_PER_BLOCK + warp;

    const float4* in4 = reinterpret_cast<const float4*>(input) + (size_t)row * VEC4_PER_ROW;
    const int4*   tg4 = reinterpret_cast<const int4*>(target)  + (size_t)row * VEC4_PER_ROW;

    float sneg = 0.0f;   // sum_{t==0} exp(x)
    float spos = 0.0f;   // sum_{t>0}  exp(-x)

    #pragma unroll 4
    for (int j = lane; j < VEC4_PER_ROW; j += 32) {
        float4 x = __ldg(&in4[j]);
        int4   t = __ldg(&tg4[j]);

        // one exp per element: e = exp(t==0 ? x : -x), branchless routing
        {
            bool neg = (t.x == 0);
            float e = __expf(neg ? x.x : -x.x);
            sneg += neg ? e : 0.0f;
            spos += neg ? 0.0f : e;
        }
        {
            bool neg = (t.y == 0);
            float e = __expf(neg ? x.y : -x.y);
            sneg += neg ? e : 0.0f;
            spos += neg ? 0.0f : e;
        }
        {
            bool neg = (t.z == 0);
            float e = __expf(neg ? x.z : -x.z);
            sneg += neg ? e : 0.0f;
            spos += neg ? 0.0f : e;
        }
        {
            bool neg = (t.w == 0);
            float e = __expf(neg ? x.w : -x.w);
            sneg += neg ? e : 0.0f;
            spos += neg ? 0.0f : e;
        }
    }

    // warp reduction of both partials
    #pragma unroll
    for (int off = 16; off > 0; off >>= 1) {
        sneg += __shfl_xor_sync(0xFFFFFFFFu, sneg, off);
        spos += __shfl_xor_sync(0xFFFFFFFFu, spos, off);
    }

    __shared__ double s_prod[WARPS_PER_BLOCK];
    if (lane == 0) {
        s_prod[warp] = (double)sneg * (double)spos;
    }
    __syncthreads();

    if (warp == 0) {
        double v = (lane < WARPS_PER_BLOCK) ? s_prod[lane] : 0.0;
        #pragma unroll
        for (int off = 4; off > 0; off >>= 1) {
            v += __shfl_xor_sync(0xFFFFFFFFu, v, off);
        }
        if (lane == 0) {
            atomicAdd(&g_total, v);
        }
    }
}

__global__ void lsep_finalize_kernel(float* __restrict__ out) {
    out[0] = (float)log1p(g_total);
    g_total = 0.0;   // reset for the next (graph-replayed) launch
}

extern "C" void kernel_launch(void* const* d_in, const int* in_sizes, int n_in,
                              void* d_out, int out_size) {
    const float* input  = (const float*)d_in[0];
    const int*   target = (const int*)d_in[1];
    float*       out    = (float*)d_out;

    lsep_main_kernel<<<ROWS / WARPS_PER_BLOCK, THREADS>>>(input, target);
    lsep_finalize_kernel<<<1, 1>>>(out);
}